// round 11
// baseline (speedup 1.0000x reference)
#include <cuda_runtime.h>
#include <cuda_bf16.h>

// Problem constants (fixed shapes for this bench)
#define B_   16
#define C_   256
#define H_   224
#define W_   224
#define P_   14
#define NH_  16
#define NW_  16
#define N_   256          // NH_*NW_ patches
#define CC_  4            // channels per tile
#define NCH_ 64           // C_/CC_
#define NTILE_ (NCH_ * B_ * NH_)   // 16384 logical tiles
#define NCTA_  1332                // 148 SMs x 9 resident CTAs
#define QSZ_  (CC_ * P_ * P_)      // 784 floats per q tile
#define EPS_COS  1e-8f
#define EPS_NORM 1e-12f

// Scratch (every consumed slot written every launch)
__device__ float g_dot[NCH_ * B_ * N_];   // [chunk][b][n]
__device__ float g_nsq[NCH_ * B_ * N_];   // [chunk][b][n]
__device__ float g_qsq[NCH_ * B_];        // [chunk][b]
__device__ float g_loss[B_];
__device__ int   g_ticket = 0;            // reset at end of each run
__device__ int   g_done   = 0;
__device__ int   g_done2  = 0;

// ---------------------------------------------------------------------------
// Single persistent kernel: ticket-scheduled accum tiles (R6 hot loop
// verbatim), then the LAST 16 CTAs to finish each finalize one batch.
// ---------------------------------------------------------------------------
__global__ __launch_bounds__(224, 9)
void fused_kernel(const float* __restrict__ qf,
                  const float* __restrict__ rf,
                  const int*   __restrict__ click,
                  const int*   __restrict__ gt,
                  const float* __restrict__ scale,
                  float* __restrict__ out) {
    __shared__ float smq[QSZ_];            // 784 floats
    __shared__ float sred[2 * 224];
    __shared__ float fl[256];              // epilogue: sims / logits
    __shared__ float fr[128];              // epilogue: reduction buffer
    __shared__ int   s_tile;
    __shared__ int   s_rank;

    const int tid = threadIdx.x;           // 0..223

    // ======================= accum phase (R6 verbatim) =====================
    for (;;) {
        __syncthreads();                   // protect s_tile/smq from prev iter
        if (tid == 0) s_tile = atomicAdd(&g_ticket, 1);
        __syncthreads();
        const int t = s_tile;
        if (t >= NTILE_) break;

        // decode: t = ((chunk*B_) + b)*NH_ + ph
        const int chunk = t >> 8;
        const int b     = (t >> 4) & 15;
        const int ph    = t & 15;
        const int c0    = chunk * CC_;

        const int qx = click[2 * b + 0];
        const int qy = click[2 * b + 1];
        const int qh = qy / P_;
        const int qw = qx / P_;

        // Stage query patch tile (CC_ x 14 x 14)
        const float* qbase = qf + ((size_t)(b * C_ + c0) * H_ + qh * P_) * W_ + qw * P_;
        for (int idx = tid; idx < QSZ_; idx += 224) {
            int cc = idx / (P_ * P_);
            int r  = idx - cc * (P_ * P_);
            int i  = r / P_;
            int j  = r - i * P_;
            smq[idx] = qbase[(cc * H_ + i) * W_ + j];
        }
        __syncthreads();

        // Stream ref rows: one column per thread, 128B/warp coalesced
        {
            const int w  = tid;
            const int pw = w / P_;
            const int j  = w - pw * P_;
            const float* tbase = rf + ((size_t)(b * C_ + c0) * H_ + ph * P_) * W_ + w;
            float dot = 0.f, nsq = 0.f;
#pragma unroll
            for (int cc = 0; cc < CC_; ++cc) {
                const float* tp = tbase + cc * (H_ * W_);
                const float* qp = smq + cc * (P_ * P_) + j;
#pragma unroll
                for (int i = 0; i < P_; ++i) {
                    float tv = __ldcs(tp + i * W_);   // streaming, evict-first
                    float qv = qp[i * P_];
                    dot = fmaf(tv, qv, dot);
                    nsq = fmaf(tv, tv, nsq);
                }
            }
            sred[w]       = dot;
            sred[224 + w] = nsq;
        }
        __syncthreads();

        // Reduce 14 columns -> one patch; disjoint slots, no atomics
        if (tid < NW_) {
            float d = 0.f, s = 0.f;
#pragma unroll
            for (int k = 0; k < P_; ++k) {
                d += sred[tid * P_ + k];
                s += sred[224 + tid * P_ + k];
            }
            const int n = ph * NW_ + tid;
            g_dot[(chunk * B_ + b) * N_ + n] = d;
            g_nsq[(chunk * B_ + b) * N_ + n] = s;
        }

        // ph==0 tiles also compute partial ||q||^2 (warp shuffle reduce)
        if (ph == 0) {
            float acc = 0.f;
            for (int idx = tid; idx < QSZ_; idx += 224) {
                float v = smq[idx];
                acc = fmaf(v, v, acc);
            }
#pragma unroll
            for (int o = 16; o > 0; o >>= 1)
                acc += __shfl_down_sync(0xffffffffu, acc, o);
            __syncthreads();               // sred readers above are done
            if ((tid & 31) == 0) sred[tid >> 5] = acc;
            __syncthreads();
            if (tid == 0) {
                float s = 0.f;
#pragma unroll
                for (int k = 0; k < 7; ++k) s += sred[k];
                g_qsq[chunk * B_ + b] = s;
            }
        }
    }

    // ======================= completion handshake ==========================
    __threadfence();                       // release all accum writes
    if (tid == 0) s_rank = atomicAdd(&g_done, 1);
    __syncthreads();
    const int rank = s_rank;
    if (rank < NCTA_ - B_) return;         // only last 16 CTAs finalize
    const int b = NCTA_ - 1 - rank;        // unique batch 0..15

    if (tid == 0) {                        // wait until ALL CTAs have fenced
        while (atomicAdd(&g_done, 0) < NCTA_) { }
    }
    __syncthreads();
    __threadfence();                       // acquire

    // ======================= finalize batch b ==============================
    // ||q||^2 = sum of 64 chunk partials
    if (tid < 64) fr[tid] = g_qsq[tid * B_ + b];
    __syncthreads();
    if (tid < 32) fr[tid] += fr[tid + 32];
    __syncthreads();
    if (tid < 16) fr[tid] += fr[tid + 16];
    __syncthreads();
    if (tid < 8)  fr[tid] += fr[tid + 8];
    __syncthreads();
    if (tid < 4)  fr[tid] += fr[tid + 4];
    __syncthreads();
    if (tid < 2)  fr[tid] += fr[tid + 2];
    __syncthreads();
    if (tid < 1)  fr[tid] += fr[tid + 1];
    __syncthreads();
    const float Qc = fmaxf(sqrtf(fr[0]), EPS_COS);
    __syncthreads();

    // cosine sims for all 256 patches (224 threads, strided)
    for (int n = tid; n < N_; n += 224) {
        float dot = 0.f, tsq = 0.f;
#pragma unroll 8
        for (int ch = 0; ch < NCH_; ++ch) {
            dot += g_dot[(ch * B_ + b) * N_ + n];
            tsq += g_nsq[(ch * B_ + b) * N_ + n];
        }
        fl[n] = dot / (fmaxf(sqrtf(tsq), EPS_COS) * Qc);
    }
    __syncthreads();

    // F.normalize over the 256-wide sim vector
    if (tid < 128) fr[tid] = fl[tid] * fl[tid] + fl[tid + 128] * fl[tid + 128];
    __syncthreads();
    for (int s = 64; s > 0; s >>= 1) {
        if (tid < s) fr[tid] += fr[tid + s];
        __syncthreads();
    }
    const float rnorm = fmaxf(sqrtf(fr[0]), EPS_NORM);
    const float sc    = scale[0];
    __syncthreads();
    for (int n = tid; n < N_; n += 224) fl[n] = sc * (fl[n] / rnorm);
    __syncthreads();

    // log-softmax: max
    if (tid < 128) fr[tid] = fmaxf(fl[tid], fl[tid + 128]);
    __syncthreads();
    for (int s = 64; s > 0; s >>= 1) {
        if (tid < s) fr[tid] = fmaxf(fr[tid], fr[tid + s]);
        __syncthreads();
    }
    const float m = fr[0];
    __syncthreads();

    // sum exp
    if (tid < 128) fr[tid] = __expf(fl[tid] - m) + __expf(fl[tid + 128] - m);
    __syncthreads();
    for (int s = 64; s > 0; s >>= 1) {
        if (tid < s) fr[tid] += fr[tid + s];
        __syncthreads();
    }
    const float lse = m + logf(fr[0]);

    if (tid == 0) {
        const int label = (gt[2 * b + 1] / P_) * NW_ + (gt[2 * b + 0] / P_);
        g_loss[b] = lse - fl[label];       // -logp[label]
        __threadfence();
        const int r2 = atomicAdd(&g_done2, 1);
        if (r2 == B_ - 1) {                // last finalizer: mean + reset
            __threadfence();
            float acc = 0.f;
#pragma unroll
            for (int k = 0; k < B_; ++k) acc += g_loss[k];
            out[0]   = acc / (float)B_;
            g_ticket = 0;                  // reset for next graph replay
            g_done   = 0;
            g_done2  = 0;
        }
    }
}

// ---------------------------------------------------------------------------
extern "C" void kernel_launch(void* const* d_in, const int* in_sizes, int n_in,
                              void* d_out, int out_size) {
    const float* qf    = (const float*)d_in[0];   // query_feature [16,256,224,224]
    const float* rf    = (const float*)d_in[1];   // ref_feature   [16,256,224,224]
    const float* scale = (const float*)d_in[2];   // logit_scale scalar
    const int*   click = (const int*)  d_in[3];   // click_points [16,2] int32
    const int*   gt    = (const int*)  d_in[4];   // gt_points    [16,2] int32
    // d_in[5] = patch_size (14), fixed -> hardcoded

    fused_kernel<<<NCTA_, 224>>>(qf, rf, click, gt, scale, (float*)d_out);
}

// round 12
// speedup vs baseline: 1.0501x; 1.0501x over previous
#include <cuda_runtime.h>
#include <cuda_bf16.h>

// Problem constants (fixed shapes for this bench)
#define B_   16
#define C_   256
#define H_   224
#define W_   224
#define P_   14
#define NH_  16
#define NW_  16
#define N_   256          // NH_*NW_ patches
#define CC_  4            // channels per tile
#define NCH_ 64           // C_/CC_
#define NTILE_ (NCH_ * B_ * NH_)   // 16384 logical tiles
#define NCTA_  1332                // 148 SMs x 9 resident CTAs
#define EPS_COS  1e-8f
#define EPS_NORM 1e-12f

// Scratch (every consumed slot written every launch)
__device__ float g_dot[NCH_ * B_ * N_];   // [chunk][b][n]
__device__ float g_nsq[NCH_ * B_ * N_];   // [chunk][b][n]
__device__ float g_qsq[NCH_ * B_];        // [chunk][b]
__device__ float g_loss[B_];
__device__ int   g_ticket = 0;            // reset by finalizeB for next replay

// ---------------------------------------------------------------------------
// Kernel 1 (persistent): ticket-scheduled tiles (chunk, b, ph).
// 224 threads = 7 warps, all streaming. Each thread owns one image column.
// Best validated configuration: 130.5us @ 80.9% DRAM (R6).
// ---------------------------------------------------------------------------
__global__ __launch_bounds__(224)
void accum_kernel(const float* __restrict__ qf,
                  const float* __restrict__ rf,
                  const int*   __restrict__ click) {
    __shared__ float smq[CC_ * P_ * P_];   // 784 floats
    __shared__ float sred[2 * 224];
    __shared__ int   s_tile;

    const int tid = threadIdx.x;           // 0..223

    for (;;) {
        __syncthreads();                   // protect s_tile/smq from prev iter
        if (tid == 0) s_tile = atomicAdd(&g_ticket, 1);
        __syncthreads();
        const int t = s_tile;
        if (t >= NTILE_) break;

        // decode: t = ((chunk*B_) + b)*NH_ + ph   (all powers of two)
        const int chunk = t >> 8;
        const int b     = (t >> 4) & 15;
        const int ph    = t & 15;
        const int c0    = chunk * CC_;

        const int qx = click[2 * b + 0];
        const int qy = click[2 * b + 1];
        const int qh = qy / P_;
        const int qw = qx / P_;

        // Stage query patch tile (CC_ x 14 x 14)
        const float* qbase = qf + ((size_t)(b * C_ + c0) * H_ + qh * P_) * W_ + qw * P_;
        for (int idx = tid; idx < CC_ * P_ * P_; idx += 224) {
            int cc = idx / (P_ * P_);
            int r  = idx - cc * (P_ * P_);
            int i  = r / P_;
            int j  = r - i * P_;
            smq[idx] = qbase[(cc * H_ + i) * W_ + j];
        }
        __syncthreads();

        // Stream ref rows: one column per thread, 128B/warp coalesced
        {
            const int w  = tid;
            const int pw = w / P_;
            const int j  = w - pw * P_;
            const float* tbase = rf + ((size_t)(b * C_ + c0) * H_ + ph * P_) * W_ + w;
            float dot = 0.f, nsq = 0.f;
#pragma unroll
            for (int cc = 0; cc < CC_; ++cc) {
                const float* tp = tbase + cc * (H_ * W_);
                const float* qp = smq + cc * (P_ * P_) + j;
#pragma unroll
                for (int i = 0; i < P_; ++i) {
                    float tv = __ldcs(tp + i * W_);   // streaming, evict-first
                    float qv = qp[i * P_];
                    dot = fmaf(tv, qv, dot);
                    nsq = fmaf(tv, tv, nsq);
                }
            }
            sred[w]       = dot;
            sred[224 + w] = nsq;
        }
        __syncthreads();

        // Reduce 14 columns -> one patch; disjoint slots, no atomics
        if (tid < NW_) {
            float d = 0.f, s = 0.f;
#pragma unroll
            for (int k = 0; k < P_; ++k) {
                d += sred[tid * P_ + k];
                s += sred[224 + tid * P_ + k];
            }
            const int n = ph * NW_ + tid;
            g_dot[(chunk * B_ + b) * N_ + n] = d;
            g_nsq[(chunk * B_ + b) * N_ + n] = s;
        }

        // ph==0 tiles also compute partial ||q||^2 (warp shuffle reduce)
        if (ph == 0) {
            float acc = 0.f;
            for (int idx = tid; idx < CC_ * P_ * P_; idx += 224) {
                float v = smq[idx];
                acc = fmaf(v, v, acc);
            }
#pragma unroll
            for (int o = 16; o > 0; o >>= 1)
                acc += __shfl_down_sync(0xffffffffu, acc, o);
            __syncthreads();               // sred readers above are done
            if ((tid & 31) == 0) sred[tid >> 5] = acc;
            __syncthreads();
            if (tid == 0) {
                float s = 0.f;
#pragma unroll
                for (int k = 0; k < 7; ++k) s += sred[k];
                g_qsq[chunk * B_ + b] = s;
            }
        }
    }
}

// ---------------------------------------------------------------------------
// Kernel 2: per-batch cosine-sim -> normalize -> log-softmax -> loss_b
// ---------------------------------------------------------------------------
__global__ __launch_bounds__(256)
void finalizeA_kernel(const float* __restrict__ logit_scale,
                      const int*   __restrict__ gt) {
    const int b   = blockIdx.x;
    const int tid = threadIdx.x;
    __shared__ float sh[256];

    // ||q||^2 = sum of chunk partials
    sh[tid] = (tid < NCH_) ? g_qsq[tid * B_ + b] : 0.f;
    __syncthreads();
    for (int s = 128; s > 0; s >>= 1) {
        if (tid < s) sh[tid] += sh[tid + s];
        __syncthreads();
    }
    const float Qc = fmaxf(sqrtf(sh[0]), EPS_COS);
    __syncthreads();

    // Per-patch (n == tid) sums across chunks
    const int n = tid;
    float dot = 0.f, tsq = 0.f;
#pragma unroll 8
    for (int ch = 0; ch < NCH_; ++ch) {
        dot += g_dot[(ch * B_ + b) * N_ + n];
        tsq += g_nsq[(ch * B_ + b) * N_ + n];
    }
    float s_n = dot / (fmaxf(sqrtf(tsq), EPS_COS) * Qc);

    // F.normalize over the 256-wide sim vector
    sh[tid] = s_n * s_n;
    __syncthreads();
    for (int s = 128; s > 0; s >>= 1) {
        if (tid < s) sh[tid] += sh[tid + s];
        __syncthreads();
    }
    const float r = fmaxf(sqrtf(sh[0]), EPS_NORM);
    __syncthreads();

    const float l = logit_scale[0] * (s_n / r);

    // log-softmax: max
    sh[tid] = l;
    __syncthreads();
    for (int s = 128; s > 0; s >>= 1) {
        if (tid < s) sh[tid] = fmaxf(sh[tid], sh[tid + s]);
        __syncthreads();
    }
    const float m = sh[0];
    __syncthreads();

    // sum exp
    sh[tid] = __expf(l - m);
    __syncthreads();
    for (int s = 128; s > 0; s >>= 1) {
        if (tid < s) sh[tid] += sh[tid + s];
        __syncthreads();
    }
    const float lse = m + logf(sh[0]);

    const int gx = gt[2 * b + 0];
    const int gy = gt[2 * b + 1];
    const int label = (gy / P_) * NW_ + (gx / P_);
    if (n == label) g_loss[b] = lse - l;   // -logp[label]
}

// ---------------------------------------------------------------------------
// Kernel 3: mean over batches + reset ticket for next graph replay
// ---------------------------------------------------------------------------
__global__ void finalizeB_kernel(float* __restrict__ out) {
    if (threadIdx.x == 0) {
        float acc = 0.f;
        for (int b = 0; b < B_; ++b) acc += g_loss[b];
        out[0] = acc / (float)B_;
        g_ticket = 0;                      // reset scheduler for next replay
    }
}

// ---------------------------------------------------------------------------
extern "C" void kernel_launch(void* const* d_in, const int* in_sizes, int n_in,
                              void* d_out, int out_size) {
    const float* qf    = (const float*)d_in[0];   // query_feature [16,256,224,224]
    const float* rf    = (const float*)d_in[1];   // ref_feature   [16,256,224,224]
    const float* scale = (const float*)d_in[2];   // logit_scale scalar
    const int*   click = (const int*)  d_in[3];   // click_points [16,2] int32
    const int*   gt    = (const int*)  d_in[4];   // gt_points    [16,2] int32
    // d_in[5] = patch_size (14), fixed -> hardcoded

    accum_kernel<<<NCTA_, 224>>>(qf, rf, click);
    finalizeA_kernel<<<B_, 256>>>(scale, gt);
    finalizeB_kernel<<<1, 32>>>((float*)d_out);
}

// round 13
// speedup vs baseline: 1.0800x; 1.0285x over previous
#include <cuda_runtime.h>
#include <cuda_bf16.h>

// Problem constants (fixed shapes for this bench)
#define B_   16
#define C_   256
#define H_   224
#define W_   224
#define P_   14
#define NH_  16
#define NW_  16
#define N_   256          // NH_*NW_ patches
#define CC_  2            // channels per tile (halved: shorter scheduler tail)
#define NCH_ 128          // C_/CC_
#define NTILE_ (NCH_ * B_ * NH_)   // 32768 logical tiles
#define NCTA_  1332                // 148 SMs x 9 resident CTAs
#define QSZ_  (CC_ * P_ * P_)      // 392 floats per q tile
#define EPS_COS  1e-8f
#define EPS_NORM 1e-12f

// Scratch (every consumed slot written every launch)
__device__ float g_dot[NCH_ * B_ * N_];   // [chunk][b][n]  (2 MB)
__device__ float g_nsq[NCH_ * B_ * N_];   // [chunk][b][n]  (2 MB)
__device__ float g_qsq[NCH_ * B_];        // [chunk][b]
__device__ float g_loss[B_];
__device__ int   g_ticket = 0;            // reset by finalizeB for next replay

// ---------------------------------------------------------------------------
// Kernel 1 (persistent): ticket-scheduled tiles (chunk, b, ph).
// 224 threads = 7 warps, all streaming. Each thread owns one image column:
// 2 channels x 14 rows = 28 coalesced scalar loads per tile.
// ---------------------------------------------------------------------------
__global__ __launch_bounds__(224)
void accum_kernel(const float* __restrict__ qf,
                  const float* __restrict__ rf,
                  const int*   __restrict__ click) {
    __shared__ float smq[QSZ_];            // 392 floats
    __shared__ float sred[2 * 224];
    __shared__ int   s_tile;

    const int tid = threadIdx.x;           // 0..223

    for (;;) {
        __syncthreads();                   // protect s_tile/smq from prev iter
        if (tid == 0) s_tile = atomicAdd(&g_ticket, 1);
        __syncthreads();
        const int t = s_tile;
        if (t >= NTILE_) break;

        // decode: t = ((chunk*B_) + b)*NH_ + ph   (B_*NH_ = 256)
        const int chunk = t >> 8;          // 0..127
        const int b     = (t >> 4) & 15;
        const int ph    = t & 15;
        const int c0    = chunk * CC_;

        const int qx = click[2 * b + 0];
        const int qy = click[2 * b + 1];
        const int qh = qy / P_;
        const int qw = qx / P_;

        // Stage query patch tile (2 channels x 14 x 14)
        const float* qbase = qf + ((size_t)(b * C_ + c0) * H_ + qh * P_) * W_ + qw * P_;
        for (int idx = tid; idx < QSZ_; idx += 224) {
            int cc = idx / (P_ * P_);
            int r  = idx - cc * (P_ * P_);
            int i  = r / P_;
            int j  = r - i * P_;
            smq[idx] = qbase[(cc * H_ + i) * W_ + j];
        }
        __syncthreads();

        // Stream ref rows: one column per thread, 128B/warp coalesced
        {
            const int w  = tid;
            const int pw = w / P_;
            const int j  = w - pw * P_;
            const float* tbase = rf + ((size_t)(b * C_ + c0) * H_ + ph * P_) * W_ + w;
            float dot = 0.f, nsq = 0.f;
#pragma unroll
            for (int cc = 0; cc < CC_; ++cc) {
                const float* tp = tbase + cc * (H_ * W_);
                const float* qp = smq + cc * (P_ * P_) + j;
#pragma unroll
                for (int i = 0; i < P_; ++i) {
                    float tv = __ldcs(tp + i * W_);   // streaming, evict-first
                    float qv = qp[i * P_];
                    dot = fmaf(tv, qv, dot);
                    nsq = fmaf(tv, tv, nsq);
                }
            }
            sred[w]       = dot;
            sred[224 + w] = nsq;
        }
        __syncthreads();

        // Reduce 14 columns -> one patch; disjoint slots, no atomics
        if (tid < NW_) {
            float d = 0.f, s = 0.f;
#pragma unroll
            for (int k = 0; k < P_; ++k) {
                d += sred[tid * P_ + k];
                s += sred[224 + tid * P_ + k];
            }
            const int n = ph * NW_ + tid;
            g_dot[(chunk * B_ + b) * N_ + n] = d;
            g_nsq[(chunk * B_ + b) * N_ + n] = s;
        }

        // ph==0 tiles also compute partial ||q||^2 (warp shuffle reduce)
        if (ph == 0) {
            float acc = 0.f;
#pragma unroll
            for (int k = 0; k < 2; ++k) {  // 392 = 224 + 168
                int idx = tid + k * 224;
                if (idx < QSZ_) {
                    float v = smq[idx];
                    acc = fmaf(v, v, acc);
                }
            }
#pragma unroll
            for (int o = 16; o > 0; o >>= 1)
                acc += __shfl_down_sync(0xffffffffu, acc, o);
            __syncthreads();               // sred readers above are done
            if ((tid & 31) == 0) sred[tid >> 5] = acc;
            __syncthreads();
            if (tid == 0) {
                float s = 0.f;
#pragma unroll
                for (int k = 0; k < 7; ++k) s += sred[k];
                g_qsq[chunk * B_ + b] = s;
            }
        }
    }
}

// ---------------------------------------------------------------------------
// Kernel 2: per-batch cosine-sim -> normalize -> log-softmax -> loss_b.
// 512 threads: two half-chunk sums per patch (64 iters each, same serial
// depth as the CC=4 version despite 128 chunks).
// ---------------------------------------------------------------------------
__global__ __launch_bounds__(512)
void finalizeA_kernel(const float* __restrict__ logit_scale,
                      const int*   __restrict__ gt) {
    const int b   = blockIdx.x;
    const int tid = threadIdx.x;           // 0..511
    __shared__ float sh[512];
    __shared__ float sd[512];
    __shared__ float st[512];

    // ||q||^2 = sum of 128 chunk partials
    sh[tid] = (tid < NCH_) ? g_qsq[tid * B_ + b] : 0.f;
    __syncthreads();
    for (int s = 256; s > 0; s >>= 1) {
        if (tid < s) sh[tid] += sh[tid + s];
        __syncthreads();
    }
    const float Qc = fmaxf(sqrtf(sh[0]), EPS_COS);
    __syncthreads();

    // Per-patch half-sums: n = tid&255, half = tid>>8 covers 64 chunks
    const int n    = tid & 255;
    const int ch0  = (tid >> 8) * 64;
    float dot = 0.f, tsq = 0.f;
#pragma unroll 8
    for (int k = 0; k < 64; ++k) {
        const int ch = ch0 + k;
        dot += g_dot[(ch * B_ + b) * N_ + n];
        tsq += g_nsq[(ch * B_ + b) * N_ + n];
    }
    sd[tid] = dot;
    st[tid] = tsq;
    __syncthreads();
    dot = sd[n] + sd[n + 256];
    tsq = st[n] + st[n + 256];
    const float s_n = dot / (fmaxf(sqrtf(tsq), EPS_COS) * Qc);

    // F.normalize over the 256-wide sim vector (count each patch once)
    sh[tid] = (tid < 256) ? s_n * s_n : 0.f;
    __syncthreads();
    for (int s = 256; s > 0; s >>= 1) {
        if (tid < s) sh[tid] += sh[tid + s];
        __syncthreads();
    }
    const float r = fmaxf(sqrtf(sh[0]), EPS_NORM);
    __syncthreads();

    const float l = logit_scale[0] * (s_n / r);

    // log-softmax: max over 256 logits
    sh[tid] = (tid < 256) ? l : -3.402823466e+38f;
    __syncthreads();
    for (int s = 256; s > 0; s >>= 1) {
        if (tid < s) sh[tid] = fmaxf(sh[tid], sh[tid + s]);
        __syncthreads();
    }
    const float m = sh[0];
    __syncthreads();

    // sum exp
    sh[tid] = (tid < 256) ? __expf(l - m) : 0.f;
    __syncthreads();
    for (int s = 256; s > 0; s >>= 1) {
        if (tid < s) sh[tid] += sh[tid + s];
        __syncthreads();
    }
    const float lse = m + logf(sh[0]);

    const int gx = gt[2 * b + 0];
    const int gy = gt[2 * b + 1];
    const int label = (gy / P_) * NW_ + (gx / P_);   // 0..255
    if (tid == label) g_loss[b] = lse - l;           // -logp[label]
}

// ---------------------------------------------------------------------------
// Kernel 3: mean over batches + reset ticket for next graph replay
// ---------------------------------------------------------------------------
__global__ void finalizeB_kernel(float* __restrict__ out) {
    if (threadIdx.x == 0) {
        float acc = 0.f;
        for (int b = 0; b < B_; ++b) acc += g_loss[b];
        out[0] = acc / (float)B_;
        g_ticket = 0;                      // reset scheduler for next replay
    }
}

// ---------------------------------------------------------------------------
extern "C" void kernel_launch(void* const* d_in, const int* in_sizes, int n_in,
                              void* d_out, int out_size) {
    const float* qf    = (const float*)d_in[0];   // query_feature [16,256,224,224]
    const float* rf    = (const float*)d_in[1];   // ref_feature   [16,256,224,224]
    const float* scale = (const float*)d_in[2];   // logit_scale scalar
    const int*   click = (const int*)  d_in[3];   // click_points [16,2] int32
    const int*   gt    = (const int*)  d_in[4];   // gt_points    [16,2] int32
    // d_in[5] = patch_size (14), fixed -> hardcoded

    accum_kernel<<<NCTA_, 224>>>(qf, rf, click);
    finalizeA_kernel<<<B_, 512>>>(scale, gt);
    finalizeB_kernel<<<1, 32>>>((float*)d_out);
}